// round 16
// baseline (speedup 1.0000x reference)
#include <cuda_runtime.h>
#include <cstdint>

// Problem dims: C=64, S=256, T=500, N=2000
// Output layout (concatenated, float32):
//   log_obs    [T,N]      at offset 0
//   log_obs_   [T,C,N]    at offset 1,000,000
//   log_hidden [T,C,S]    at offset 65,000,000

static __device__ float g_Ppow[64 * 256 * 256];   // g_Ppow[i] = P^(i+1)
static __device__ float g_Ppt[64 * 256 * 256];    // transposed powers
static __device__ float g_Q[8 * 256 * 256];       // slots 2 (Q^2) and 4 (Q^4)
static __device__ float g_p[500 * 64 * 256];      // probabilities p_t
static __device__ float g_E[256 * 2000];          // Ee = E/colmax
static __device__ float g_Et[2048 * 256];         // Ee transposed, zero padded
static __device__ float g_bmaxE[2048];            // log(colmax of E)
static __device__ float g_w[500 * 64];            // softmax chain weights
static __device__ float g_wp[500 * 256];          // wp[t,s]

#define QPOW(k) (g_Q + (size_t)(k) * 65536)
#define P64     (g_Ppow + (size_t)63 * 65536)

// shared pool for F kernels: max(fill: 64*36 + 256*36 + 64, qb: 2*64*68) = 11584 floats
#define FPOOL_FLOATS 11584

// ================= block reductions =================
__device__ __forceinline__ float bredMax(float v) {
    __shared__ float sm[8];
    unsigned nw = blockDim.x >> 5;
#pragma unroll
    for (int o = 16; o; o >>= 1) v = fmaxf(v, __shfl_xor_sync(0xffffffffu, v, o));
    if ((threadIdx.x & 31) == 0) sm[threadIdx.x >> 5] = v;
    __syncthreads();
    if (threadIdx.x < 32) {
        v = (threadIdx.x < nw) ? sm[threadIdx.x] : -3.402823e38f;
#pragma unroll
        for (int o = 4; o; o >>= 1) v = fmaxf(v, __shfl_xor_sync(0xffffffffu, v, o));
        if (threadIdx.x == 0) sm[0] = v;
    }
    __syncthreads();
    v = sm[0];
    __syncthreads();
    return v;
}
__device__ __forceinline__ float bredSum(float v) {
    __shared__ float sm[8];
    unsigned nw = blockDim.x >> 5;
#pragma unroll
    for (int o = 16; o; o >>= 1) v += __shfl_xor_sync(0xffffffffu, v, o);
    if ((threadIdx.x & 31) == 0) sm[threadIdx.x >> 5] = v;
    __syncthreads();
    if (threadIdx.x < 32) {
        v = (threadIdx.x < nw) ? sm[threadIdx.x] : 0.f;
#pragma unroll
        for (int o = 4; o; o >>= 1) v += __shfl_xor_sync(0xffffffffu, v, o);
        if (threadIdx.x == 0) sm[0] = v;
    }
    __syncthreads();
    v = sm[0];
    __syncthreads();
    return v;
}

// ================= 32x64 fp32 GEMM tile over K=256 (256 threads) =================
__device__ void gemm_tile32(const float* __restrict__ A, const float* __restrict__ B,
                            float* __restrict__ Cm, float* __restrict__ Ct,
                            int r0, int c0, float (*As)[68], float (*Bs)[68]) {
    const int u = threadIdx.x;
    const int tx = u & 15, ty = u >> 4;
    float acc[2][4];
#pragma unroll
    for (int i = 0; i < 2; i++)
#pragma unroll
        for (int j = 0; j < 4; j++) acc[i][j] = 0.f;
    for (int k0 = 0; k0 < 256; k0 += 64) {
#pragma unroll
        for (int q = 0; q < 2; q++) {
            int f = q * 256 + u;
            int row = f >> 4, kq = (f & 15) << 2;
            *(float4*)&As[row][kq] = *(const float4*)&A[(size_t)(r0 + row) * 256 + k0 + kq];
        }
#pragma unroll
        for (int q = 0; q < 4; q++) {
            int f = q * 256 + u;
            int row = f >> 4, kq = (f & 15) << 2;
            *(float4*)&Bs[row][kq] = *(const float4*)&B[(size_t)(k0 + row) * 256 + c0 + kq];
        }
        __syncthreads();
#pragma unroll
        for (int k2 = 0; k2 < 64; k2++) {
            float a0 = As[ty * 2 + 0][k2], a1 = As[ty * 2 + 1][k2];
            float4 b = *(const float4*)&Bs[k2][tx * 4];
            acc[0][0] += a0 * b.x; acc[0][1] += a0 * b.y; acc[0][2] += a0 * b.z; acc[0][3] += a0 * b.w;
            acc[1][0] += a1 * b.x; acc[1][1] += a1 * b.y; acc[1][2] += a1 * b.z; acc[1][3] += a1 * b.w;
        }
        __syncthreads();
    }
#pragma unroll
    for (int i = 0; i < 2; i++) {
        *(float4*)&Cm[(size_t)(r0 + ty * 2 + i) * 256 + c0 + tx * 4] =
            make_float4(acc[i][0], acc[i][1], acc[i][2], acc[i][3]);
        if (Ct)
#pragma unroll
            for (int j = 0; j < 4; j++)
                Ct[(size_t)(c0 + tx * 4 + j) * 256 + r0 + ty * 2 + i] = acc[i][j];
    }
}

// ================= stage 0: softmaxes (383) || E row softmax (256) =================
__global__ __launch_bounds__(256) void k_stage0(const float* __restrict__ usi,
                                                const float* __restrict__ ucw,
                                                const float* __restrict__ utm,
                                                const float* __restrict__ uem,
                                                const float* __restrict__ msk,
                                                float* __restrict__ hid) {
    const int b = blockIdx.x;
    const int u = threadIdx.x;
    if (b < 256) {
        float v = utm[b * 256 + u];
        float m = bredMax(v);
        float e = __expf(v - m);
        float Z = bredSum(e);
        float p = e / Z;
        g_Ppow[b * 256 + u] = p;
        g_Ppt[u * 256 + b] = p;
    } else if (b < 320) {
        int r = b - 256;
        float v = usi[r * 256 + u];
        float m = bredMax(v);
        float e = __expf(v - m);
        float Z = bredSum(e);
        g_p[r * 256 + u] = e / Z;
        hid[r * 256 + u] = (v - m) - __logf(Z);
    } else if (b < 383) {
        int wid = u >> 5, lane = u & 31;
        int r = (b - 320) * 8 + wid;
        if (r < 500) {
            float v0 = ucw[r * 64 + lane], v1 = ucw[r * 64 + lane + 32];
            float m = fmaxf(v0, v1);
#pragma unroll
            for (int o = 16; o; o >>= 1) m = fmaxf(m, __shfl_xor_sync(0xffffffffu, m, o));
            float e0 = __expf(v0 - m), e1 = __expf(v1 - m);
            float s = e0 + e1;
#pragma unroll
            for (int o = 16; o; o >>= 1) s += __shfl_xor_sync(0xffffffffu, s, o);
            g_w[r * 64 + lane] = e0 / s;
            g_w[r * 64 + lane + 32] = e1 / s;
        }
    } else {
        int s = b - 383;
        const float* xr = uem + (size_t)s * 2000;
        const float* mr = msk + (size_t)s * 2000;
        float* Er = g_E + (size_t)s * 2000;
        float m = -3.402823e38f;
        for (int n = u; n < 2000; n += 256)
            if (mr[n] > 0.f) m = fmaxf(m, xr[n]);
        m = bredMax(m);
        float sloc = 0.f;
        for (int n = u; n < 2000; n += 256) {
            float e = (mr[n] > 0.f) ? __expf(xr[n] - m) * mr[n] : 0.f;
            Er[n] = e;
            sloc += e;
        }
        float Z = bredSum(sloc);
        float inv = 1.f / Z;
        for (int n = u; n < 2000; n += 256) Er[n] *= inv;
    }
}

// ================= stage 1: E colmax (8) || pmul dst=1 (32 tiles) =================
__global__ __launch_bounds__(256) void k_stage1() {
    const int b = blockIdx.x;
    if (b < 8) {
        int n = b * 256 + threadIdx.x;
        if (n >= 2000) return;
        float m = 0.f;
        for (int s = 0; s < 256; s++) m = fmaxf(m, g_E[(size_t)s * 2000 + n]);
        g_bmaxE[n] = __logf(m);
        float inv = 1.f / m;
        for (int s = 0; s < 256; s++) g_E[(size_t)s * 2000 + n] *= inv;
    } else {
        __shared__ float As[64][68];
        __shared__ float Bs[64][68];
        int rc = b - 8;  // 0..31
        gemm_tile32(g_Ppow, g_Ppow, g_Ppow + 65536, g_Ppt + 65536,
                    (rc >> 2) * 32, (rc & 3) * 64, As, Bs);
    }
}

// ================= stage 2: E transpose (504) || pmul dst=2 count=2 (64 tiles) =================
__global__ __launch_bounds__(256) void k_stage2() {
    const int b = blockIdx.x;
    if (b < 504) {
        __shared__ float tile[32][33];
        const int nb = (b % 63) * 32, sb = (b / 63) * 32;
        const int tx = threadIdx.x & 31, tr = threadIdx.x >> 5;
#pragma unroll
        for (int i = tr; i < 32; i += 8) {
            int n = nb + tx;
            tile[i][tx] = (n < 2000) ? g_E[(size_t)(sb + i) * 2000 + n] : 0.f;
        }
        __syncthreads();
#pragma unroll
        for (int i = tr; i < 32; i += 8)
            g_Et[(size_t)(nb + i) * 256 + sb + tx] = tile[tx][i];
    } else {
        __shared__ float As[64][68];
        __shared__ float Bs[64][68];
        int q = b - 504;                 // 0..63
        int z = q >> 5, rc = q & 31;
        gemm_tile32(g_Ppow + (size_t)z * 65536, g_Ppow + 65536,
                    g_Ppow + (size_t)(2 + z) * 65536, g_Ppt + (size_t)(2 + z) * 65536,
                    (rc >> 2) * 32, (rc & 3) * 64, As, Bs);
    }
}

// ================= 512-thread 64x64 ladder tile: Ppow[dst+z] = Ppow[z] @ Ppow[dst-1] =================
// grid (4, 4, count), 16 warps, 8 outputs/thread (2 rows x 4 cols)
__global__ __launch_bounds__(512) void k_pmulW(int dst) {
    __shared__ float As[64][68];
    __shared__ float Bs[64][68];
    const int z = blockIdx.z;
    const float* A = g_Ppow + (size_t)z * 65536;
    const float* B = g_Ppow + (size_t)(dst - 1) * 65536;
    float* Cm = g_Ppow + (size_t)(dst + z) * 65536;
    float* Ct = g_Ppt + (size_t)(dst + z) * 65536;
    const int r0 = blockIdx.y * 64, c0 = blockIdx.x * 64;
    const int u = threadIdx.x;
    const int tx = u & 15, ty = u >> 4;  // ty 0..31

    float acc[2][4];
#pragma unroll
    for (int i = 0; i < 2; i++)
#pragma unroll
        for (int j = 0; j < 4; j++) acc[i][j] = 0.f;

    for (int k0 = 0; k0 < 256; k0 += 64) {
#pragma unroll
        for (int q = 0; q < 2; q++) {
            int f = q * 512 + u;             // 0..1023
            int row = f >> 4, kq = (f & 15) << 2;
            *(float4*)&As[row][kq] = *(const float4*)&A[(size_t)(r0 + row) * 256 + k0 + kq];
            *(float4*)&Bs[row][kq] = *(const float4*)&B[(size_t)(k0 + row) * 256 + c0 + kq];
        }
        __syncthreads();
#pragma unroll
        for (int k2 = 0; k2 < 64; k2++) {
            float a0 = As[ty * 2 + 0][k2], a1 = As[ty * 2 + 1][k2];
            float4 b = *(const float4*)&Bs[k2][tx * 4];
            acc[0][0] += a0 * b.x; acc[0][1] += a0 * b.y; acc[0][2] += a0 * b.z; acc[0][3] += a0 * b.w;
            acc[1][0] += a1 * b.x; acc[1][1] += a1 * b.y; acc[1][2] += a1 * b.z; acc[1][3] += a1 * b.w;
        }
        __syncthreads();
    }
#pragma unroll
    for (int i = 0; i < 2; i++) {
        *(float4*)&Cm[(size_t)(r0 + ty * 2 + i) * 256 + c0 + tx * 4] =
            make_float4(acc[i][0], acc[i][1], acc[i][2], acc[i][3]);
#pragma unroll
        for (int j = 0; j < 4; j++)
            Ct[(size_t)(c0 + tx * 4 + j) * 256 + r0 + ty * 2 + i] = acc[i][j];
    }
}

// ================= tf32 mma.sync =================
__device__ __forceinline__ void mma_tf32(float* c, const uint32_t* a, const uint32_t* b) {
    asm volatile(
        "mma.sync.aligned.m16n8k8.row.col.f32.tf32.tf32.f32 "
        "{%0,%1,%2,%3}, {%4,%5,%6,%7}, {%8,%9}, {%0,%1,%2,%3};"
        : "+f"(c[0]), "+f"(c[1]), "+f"(c[2]), "+f"(c[3])
        : "r"(a[0]), "r"(a[1]), "r"(a[2]), "r"(a[3]), "r"(b[0]), "r"(b[1]));
}

// Fill one t (256 threads): p_t[64,256] = p_base @ P^i (tf32 MMA), hid = log, wp[t,:].
__device__ void fill_t(int t, float* __restrict__ hid, float* __restrict__ pool) {
    float (*sA)[36] = (float(*)[36])pool;                  // 64 x 36
    float (*sB)[36] = (float(*)[36])(pool + 64 * 36);      // 256 x 36
    float* sw = pool + 64 * 36 + 256 * 36;                 // 64
    const int u = threadIdx.x;
    const int lane = u & 31;
    const int w = u >> 5;
    const int wm = w & 1;
    const int wn = w >> 1;
    const int base = ((t - 1) >> 6) << 6;
    const int i = t - base;
    const float* A = g_p + (size_t)base * 16384;
    const float* Bt = g_Ppt + (size_t)(i - 1) * 65536;

    if (u < 64) sw[u] = g_w[t * 64 + u];

    float acc[2][8][4];
#pragma unroll
    for (int mt = 0; mt < 2; mt++)
#pragma unroll
        for (int nt = 0; nt < 8; nt++)
#pragma unroll
            for (int r = 0; r < 4; r++) acc[mt][nt][r] = 0.f;

    const int lr = lane >> 2;
    const int lc = lane & 3;

    for (int ch = 0; ch < 8; ch++) {
        const int k0 = ch * 32;
#pragma unroll
        for (int q = 0; q < 2; q++) {
            int f = q * 256 + u;
            int row = f >> 3, c4 = (f & 7) << 2;
            *(float4*)&sA[row][c4] = *(const float4*)&A[(size_t)row * 256 + k0 + c4];
        }
#pragma unroll
        for (int q = 0; q < 8; q++) {
            int f = q * 256 + u;
            int row = f >> 3, c4 = (f & 7) << 2;
            *(float4*)&sB[row][c4] = *(const float4*)&Bt[(size_t)row * 256 + k0 + c4];
        }
        __syncthreads();
#pragma unroll
        for (int k8 = 0; k8 < 4; k8++) {
            const int kb = k8 * 8;
            uint32_t bfr[8][2];
#pragma unroll
            for (int nt = 0; nt < 8; nt++) {
                const int nrow = wn * 64 + nt * 8 + lr;
                bfr[nt][0] = __float_as_uint(sB[nrow][kb + lc]);
                bfr[nt][1] = __float_as_uint(sB[nrow][kb + lc + 4]);
            }
#pragma unroll
            for (int mt = 0; mt < 2; mt++) {
                const int arow = wm * 32 + mt * 16 + lr;
                uint32_t afr[4];
                afr[0] = __float_as_uint(sA[arow][kb + lc]);
                afr[1] = __float_as_uint(sA[arow + 8][kb + lc]);
                afr[2] = __float_as_uint(sA[arow][kb + lc + 4]);
                afr[3] = __float_as_uint(sA[arow + 8][kb + lc + 4]);
#pragma unroll
                for (int nt = 0; nt < 8; nt++) mma_tf32(acc[mt][nt], afr, bfr[nt]);
            }
        }
        __syncthreads();
    }

    float* pout = g_p + (size_t)t * 16384;
    float* hout = hid + (size_t)t * 16384;
#pragma unroll
    for (int mt = 0; mt < 2; mt++) {
        const int row = wm * 32 + mt * 16 + lr;
#pragma unroll
        for (int nt = 0; nt < 8; nt++) {
            const int col = wn * 64 + nt * 8 + 2 * lc;
            float2 v0 = make_float2(acc[mt][nt][0], acc[mt][nt][1]);
            float2 v1 = make_float2(acc[mt][nt][2], acc[mt][nt][3]);
            *(float2*)&pout[(size_t)row * 256 + col] = v0;
            *(float2*)&pout[(size_t)(row + 8) * 256 + col] = v1;
            *(float2*)&hout[(size_t)row * 256 + col] = make_float2(__logf(v0.x), __logf(v0.y));
            *(float2*)&hout[(size_t)(row + 8) * 256 + col] = make_float2(__logf(v1.x), __logf(v1.y));
        }
    }

    // wp epilogue: wp[t, col] = sum over 64 rows of w[row]*p[row, col]
    float* red = &sB[0][0];  // 16 groups x 256 cols = 4096 floats
    const int g = wm * 8 + lr;
    float w0 = sw[wm * 32 + lr],      w0b = sw[wm * 32 + lr + 8];
    float w1 = sw[wm * 32 + 16 + lr], w1b = sw[wm * 32 + 16 + lr + 8];
    __syncthreads();
#pragma unroll
    for (int nt = 0; nt < 8; nt++) {
        const int col = wn * 64 + nt * 8 + 2 * lc;
#pragma unroll
        for (int d = 0; d < 2; d++) {
            float part = w0 * acc[0][nt][d] + w0b * acc[0][nt][d + 2] +
                         w1 * acc[1][nt][d] + w1b * acc[1][nt][d + 2];
            red[g * 256 + col + d] = part;
        }
    }
    __syncthreads();
#pragma unroll
    for (int h = 8; h > 0; h >>= 1) {
        for (int e = u; e < h * 256; e += 256) red[e] += red[e + h * 256];
        __syncthreads();
    }
    g_wp[(size_t)t * 256 + u] = red[u];
}

// ===== Merged qb + fill launches =====
// F1: Q2 (32 tiles) || fill t=1..64 (64) || wp[0,:] (1). grid 97.
__global__ __launch_bounds__(256) void k_F1(float* __restrict__ hid) {
    __shared__ float pool[FPOOL_FLOATS];
    const int b = blockIdx.x;
    if (b < 32) {
        gemm_tile32(P64, P64, QPOW(2), nullptr, (b >> 2) * 32, (b & 3) * 64,
                    (float(*)[68])pool, (float(*)[68])(pool + 64 * 68));
    } else if (b < 96) {
        fill_t(b - 31, hid, pool);
    } else {
        int s = threadIdx.x;
        float a = 0.f;
#pragma unroll 8
        for (int c = 0; c < 64; c++) a += g_w[c] * g_p[c * 256 + s];
        g_wp[s] = a;
    }
}

// F2: Q4 = Q2@Q2 (32) || p192 = p64@Q2 (8) || fill t=65..128 (64). grid 104.
__global__ __launch_bounds__(256) void k_F2(float* __restrict__ hid) {
    __shared__ float pool[FPOOL_FLOATS];
    const int b = blockIdx.x;
    if (b < 32) {
        gemm_tile32(QPOW(2), QPOW(2), QPOW(4), nullptr, (b >> 2) * 32, (b & 3) * 64,
                    (float(*)[68])pool, (float(*)[68])(pool + 64 * 68));
    } else if (b < 40) {
        int q = b - 32;  // 0..7
        gemm_tile32(g_p + (size_t)64 * 16384, QPOW(2), g_p + (size_t)192 * 16384, nullptr,
                    (q >> 2) * 32, (q & 3) * 64,
                    (float(*)[68])pool, (float(*)[68])(pool + 64 * 68));
    } else {
        fill_t(b - 40 + 65, hid, pool);
    }
}

// F3: p[256+64j] = p[64j]@Q4, j=0..3 (32 tiles) || fill t=129..256 (128). grid 160.
__global__ __launch_bounds__(256) void k_F3(float* __restrict__ hid) {
    __shared__ float pool[FPOOL_FLOATS];
    const int b = blockIdx.x;
    if (b < 32) {
        int j = b >> 3, q = b & 7;
        gemm_tile32(g_p + (size_t)(64 * j) * 16384, QPOW(4),
                    g_p + (size_t)(256 + 64 * j) * 16384, nullptr,
                    (q >> 2) * 32, (q & 3) * 64,
                    (float(*)[68])pool, (float(*)[68])(pool + 64 * 68));
    } else {
        fill_t(b - 32 + 129, hid, pool);
    }
}

// F4: fill t=257..499. grid 243.
__global__ __launch_bounds__(256) void k_F4(float* __restrict__ hid) {
    __shared__ float pool[FPOOL_FLOATS];
    fill_t(blockIdx.x + 257, hid, pool);
}

// ================= emission GEMM + obs (fused, R11-exact) =================
__global__ __launch_bounds__(256) void k_emis_obs(float* __restrict__ out) {
    __shared__ float pool2[2 * 128 * 36 + 128];
    const int u = threadIdx.x;

    if (blockIdx.y >= 250) {
        float* wsm = pool2;
        const int idx = (blockIdx.y - 250) * 16 + blockIdx.x;
        const int t0 = (idx >> 3) * 16;
        const int n = (idx & 7) * 256 + u;
#pragma unroll
        for (int j = 0; j < 16; j++)
            wsm[j * 256 + u] = (t0 + j < 500) ? g_wp[(size_t)(t0 + j) * 256 + u] : 0.f;
        __syncthreads();
        float acc[16];
#pragma unroll
        for (int j = 0; j < 16; j++) acc[j] = 0.f;
        for (int s = 0; s < 256; s++) {
            float e = (n < 2000) ? g_E[(size_t)s * 2000 + n] : 0.f;
#pragma unroll
            for (int j = 0; j < 16; j++) acc[j] += wsm[j * 256 + s] * e;
        }
        if (n < 2000) {
            float bm = g_bmaxE[n];
#pragma unroll
            for (int j = 0; j < 16; j++)
                if (t0 + j < 500) out[(size_t)(t0 + j) * 2000 + n] = __logf(acc[j]) + bm;
        }
        return;
    }

    float (*sA)[36] = (float(*)[36])pool2;
    float (*sB)[36] = (float(*)[36])(pool2 + 128 * 36);
    float* sBM = pool2 + 2 * 128 * 36;

    const int lane = u & 31;
    const int w = u >> 5;
    const int wm = w & 3;
    const int wn = w >> 2;
    const int n0 = blockIdx.x * 128;
    const int r0 = blockIdx.y * 128;

    if (u < 128) sBM[u] = g_bmaxE[n0 + u];

    float acc[2][8][4];
#pragma unroll
    for (int mt = 0; mt < 2; mt++)
#pragma unroll
        for (int nt = 0; nt < 8; nt++)
#pragma unroll
            for (int r = 0; r < 4; r++) acc[mt][nt][r] = 0.f;

    const int lr = lane >> 2;
    const int lc = lane & 3;

    for (int ch = 0; ch < 8; ch++) {
        const int k0 = ch * 32;
#pragma unroll
        for (int q = 0; q < 4; q++) {
            int f = q * 256 + u;
            int row = f >> 3, c4 = (f & 7) << 2;
            *(float4*)&sA[row][c4] = *(const float4*)&g_p[(size_t)(r0 + row) * 256 + k0 + c4];
            *(float4*)&sB[row][c4] = *(const float4*)&g_Et[(size_t)(n0 + row) * 256 + k0 + c4];
        }
        __syncthreads();
#pragma unroll
        for (int k8 = 0; k8 < 4; k8++) {
            const int kb = k8 * 8;
            uint32_t bfr[8][2];
#pragma unroll
            for (int nt = 0; nt < 8; nt++) {
                const int nrow = wn * 64 + nt * 8 + lr;
                bfr[nt][0] = __float_as_uint(sB[nrow][kb + lc]);
                bfr[nt][1] = __float_as_uint(sB[nrow][kb + lc + 4]);
            }
#pragma unroll
            for (int mt = 0; mt < 2; mt++) {
                const int arow = wm * 32 + mt * 16 + lr;
                uint32_t afr[4];
                afr[0] = __float_as_uint(sA[arow][kb + lc]);
                afr[1] = __float_as_uint(sA[arow + 8][kb + lc]);
                afr[2] = __float_as_uint(sA[arow][kb + lc + 4]);
                afr[3] = __float_as_uint(sA[arow + 8][kb + lc + 4]);
#pragma unroll
                for (int nt = 0; nt < 8; nt++) mma_tf32(acc[mt][nt], afr, bfr[nt]);
            }
        }
        __syncthreads();
    }

    float* obsp = out + 1000000u;
#pragma unroll
    for (int mt = 0; mt < 2; mt++) {
        const int row = r0 + wm * 32 + mt * 16 + lr;
#pragma unroll
        for (int nt = 0; nt < 8; nt++) {
            const int col = wn * 64 + nt * 8 + 2 * lc;
            const int n = n0 + col;
            if (n < 2000) {
                float2 v0, v1;
                v0.x = __logf(acc[mt][nt][0]) + sBM[col];
                v0.y = __logf(acc[mt][nt][1]) + sBM[col + 1];
                v1.x = __logf(acc[mt][nt][2]) + sBM[col];
                v1.y = __logf(acc[mt][nt][3]) + sBM[col + 1];
                *(float2*)&obsp[(size_t)row * 2000 + n] = v0;
                *(float2*)&obsp[(size_t)(row + 8) * 2000 + n] = v1;
            }
        }
    }
}

// ================= launch =================
extern "C" void kernel_launch(void* const* d_in, const int* in_sizes, int n_in,
                              void* d_out, int out_size) {
    const float* usi = (const float*)d_in[0];  // [64,256]
    const float* ucw = (const float*)d_in[1];  // [500,64]
    const float* uem = (const float*)d_in[2];  // [256,2000]
    const float* utm = (const float*)d_in[3];  // [256,256]
    const float* msk = (const float*)d_in[4];  // [256,2000]
    float* out = (float*)d_out;
    float* hid = out + 65000000u;

    k_stage0<<<639, 256>>>(usi, ucw, utm, uem, msk, hid);
    k_stage1<<<40, 256>>>();
    k_stage2<<<568, 256>>>();

    k_pmulW<<<dim3(4, 4, 4), 512>>>(4);    // P^5..8
    k_pmulW<<<dim3(4, 4, 8), 512>>>(8);    // P^9..16
    k_pmulW<<<dim3(4, 4, 16), 512>>>(16);  // P^17..32
    k_pmulW<<<dim3(4, 4, 32), 512>>>(32);  // P^33..64

    k_F1<<<97, 256>>>(hid);
    k_F2<<<104, 256>>>(hid);
    k_F3<<<160, 256>>>(hid);
    k_F4<<<243, 256>>>(hid);

    k_emis_obs<<<dim3(16, 266), 256>>>(out);
}

// round 17
// speedup vs baseline: 1.0798x; 1.0798x over previous
#include <cuda_runtime.h>
#include <cstdint>

// Problem dims: C=64, S=256, T=500, N=2000
// Output layout (concatenated, float32):
//   log_obs    [T,N]      at offset 0
//   log_obs_   [T,C,N]    at offset 1,000,000
//   log_hidden [T,C,S]    at offset 65,000,000

static __device__ float g_Ppow[64 * 256 * 256];   // g_Ppow[i] = P^(i+1)
static __device__ float g_Ppt[64 * 256 * 256];    // transposed powers
static __device__ float g_Q[8 * 256 * 256];       // slots 2 (Q^2) and 4 (Q^4)
static __device__ float g_p[500 * 64 * 256];      // probabilities p_t
static __device__ float g_E[256 * 2000];          // Ee = E/colmax
static __device__ float g_Et[2048 * 256];         // Ee transposed, zero padded
static __device__ float g_bmaxE[2048];            // log(colmax of E)
static __device__ float g_w[500 * 64];            // softmax chain weights
static __device__ float g_wp[500 * 256];          // wp[t,s]

// ================= block reductions =================
__device__ __forceinline__ float bredMax(float v) {
    __shared__ float sm[8];
    unsigned nw = blockDim.x >> 5;
#pragma unroll
    for (int o = 16; o; o >>= 1) v = fmaxf(v, __shfl_xor_sync(0xffffffffu, v, o));
    if ((threadIdx.x & 31) == 0) sm[threadIdx.x >> 5] = v;
    __syncthreads();
    if (threadIdx.x < 32) {
        v = (threadIdx.x < nw) ? sm[threadIdx.x] : -3.402823e38f;
#pragma unroll
        for (int o = 4; o; o >>= 1) v = fmaxf(v, __shfl_xor_sync(0xffffffffu, v, o));
        if (threadIdx.x == 0) sm[0] = v;
    }
    __syncthreads();
    v = sm[0];
    __syncthreads();
    return v;
}
__device__ __forceinline__ float bredSum(float v) {
    __shared__ float sm[8];
    unsigned nw = blockDim.x >> 5;
#pragma unroll
    for (int o = 16; o; o >>= 1) v += __shfl_xor_sync(0xffffffffu, v, o);
    if ((threadIdx.x & 31) == 0) sm[threadIdx.x >> 5] = v;
    __syncthreads();
    if (threadIdx.x < 32) {
        v = (threadIdx.x < nw) ? sm[threadIdx.x] : 0.f;
#pragma unroll
        for (int o = 4; o; o >>= 1) v += __shfl_xor_sync(0xffffffffu, v, o);
        if (threadIdx.x == 0) sm[0] = v;
    }
    __syncthreads();
    v = sm[0];
    __syncthreads();
    return v;
}

// ================= 64x64 fp32 GEMM tile over K=256 =================
__device__ void gemm_tile(const float* __restrict__ A, const float* __restrict__ B,
                          float* __restrict__ Cm, float* __restrict__ Ct,
                          int r0, int c0, float (*As)[68], float (*Bs)[68]) {
    const int u = threadIdx.x;
    const int tx = u & 15, ty = u >> 4;
    float acc[4][4];
#pragma unroll
    for (int i = 0; i < 4; i++)
#pragma unroll
        for (int j = 0; j < 4; j++) acc[i][j] = 0.f;
    for (int k0 = 0; k0 < 256; k0 += 64) {
#pragma unroll
        for (int q = 0; q < 4; q++) {
            int f = q * 256 + u;
            int row = f >> 4, kq = (f & 15) << 2;
            *(float4*)&As[row][kq] = *(const float4*)&A[(size_t)(r0 + row) * 256 + k0 + kq];
            *(float4*)&Bs[row][kq] = *(const float4*)&B[(size_t)(k0 + row) * 256 + c0 + kq];
        }
        __syncthreads();
#pragma unroll
        for (int k2 = 0; k2 < 64; k2++) {
            float a0 = As[ty * 4 + 0][k2], a1 = As[ty * 4 + 1][k2];
            float a2 = As[ty * 4 + 2][k2], a3 = As[ty * 4 + 3][k2];
            float4 b = *(const float4*)&Bs[k2][tx * 4];
            acc[0][0] += a0 * b.x; acc[0][1] += a0 * b.y; acc[0][2] += a0 * b.z; acc[0][3] += a0 * b.w;
            acc[1][0] += a1 * b.x; acc[1][1] += a1 * b.y; acc[1][2] += a1 * b.z; acc[1][3] += a1 * b.w;
            acc[2][0] += a2 * b.x; acc[2][1] += a2 * b.y; acc[2][2] += a2 * b.z; acc[2][3] += a2 * b.w;
            acc[3][0] += a3 * b.x; acc[3][1] += a3 * b.y; acc[3][2] += a3 * b.z; acc[3][3] += a3 * b.w;
        }
        __syncthreads();
    }
#pragma unroll
    for (int i = 0; i < 4; i++) {
        *(float4*)&Cm[(size_t)(r0 + ty * 4 + i) * 256 + c0 + tx * 4] =
            make_float4(acc[i][0], acc[i][1], acc[i][2], acc[i][3]);
        if (Ct)
#pragma unroll
            for (int j = 0; j < 4; j++)
                Ct[(size_t)(c0 + tx * 4 + j) * 256 + r0 + ty * 4 + i] = acc[i][j];
    }
}

// ================= 32x64 fp32 GEMM tile over K=256 =================
__device__ void gemm_tile32(const float* __restrict__ A, const float* __restrict__ B,
                            float* __restrict__ Cm, float* __restrict__ Ct,
                            int r0, int c0, float (*As)[68], float (*Bs)[68]) {
    const int u = threadIdx.x;
    const int tx = u & 15, ty = u >> 4;
    float acc[2][4];
#pragma unroll
    for (int i = 0; i < 2; i++)
#pragma unroll
        for (int j = 0; j < 4; j++) acc[i][j] = 0.f;
    for (int k0 = 0; k0 < 256; k0 += 64) {
#pragma unroll
        for (int q = 0; q < 2; q++) {
            int f = q * 256 + u;
            int row = f >> 4, kq = (f & 15) << 2;
            *(float4*)&As[row][kq] = *(const float4*)&A[(size_t)(r0 + row) * 256 + k0 + kq];
        }
#pragma unroll
        for (int q = 0; q < 4; q++) {
            int f = q * 256 + u;
            int row = f >> 4, kq = (f & 15) << 2;
            *(float4*)&Bs[row][kq] = *(const float4*)&B[(size_t)(k0 + row) * 256 + c0 + kq];
        }
        __syncthreads();
#pragma unroll
        for (int k2 = 0; k2 < 64; k2++) {
            float a0 = As[ty * 2 + 0][k2], a1 = As[ty * 2 + 1][k2];
            float4 b = *(const float4*)&Bs[k2][tx * 4];
            acc[0][0] += a0 * b.x; acc[0][1] += a0 * b.y; acc[0][2] += a0 * b.z; acc[0][3] += a0 * b.w;
            acc[1][0] += a1 * b.x; acc[1][1] += a1 * b.y; acc[1][2] += a1 * b.z; acc[1][3] += a1 * b.w;
        }
        __syncthreads();
    }
#pragma unroll
    for (int i = 0; i < 2; i++) {
        *(float4*)&Cm[(size_t)(r0 + ty * 2 + i) * 256 + c0 + tx * 4] =
            make_float4(acc[i][0], acc[i][1], acc[i][2], acc[i][3]);
        if (Ct)
#pragma unroll
            for (int j = 0; j < 4; j++)
                Ct[(size_t)(c0 + tx * 4 + j) * 256 + r0 + ty * 2 + i] = acc[i][j];
    }
}

// ================= stage 0: softmaxes (383) || E row softmax (256) =================
__global__ __launch_bounds__(256) void k_stage0(const float* __restrict__ usi,
                                                const float* __restrict__ ucw,
                                                const float* __restrict__ utm,
                                                const float* __restrict__ uem,
                                                const float* __restrict__ msk,
                                                float* __restrict__ hid) {
    const int b = blockIdx.x;
    const int u = threadIdx.x;
    if (b < 256) {
        float v = utm[b * 256 + u];
        float m = bredMax(v);
        float e = __expf(v - m);
        float Z = bredSum(e);
        float p = e / Z;
        g_Ppow[b * 256 + u] = p;
        g_Ppt[u * 256 + b] = p;
    } else if (b < 320) {
        int r = b - 256;
        float v = usi[r * 256 + u];
        float m = bredMax(v);
        float e = __expf(v - m);
        float Z = bredSum(e);
        g_p[r * 256 + u] = e / Z;
        hid[r * 256 + u] = (v - m) - __logf(Z);
    } else if (b < 383) {
        int wid = u >> 5, lane = u & 31;
        int r = (b - 320) * 8 + wid;
        if (r < 500) {
            float v0 = ucw[r * 64 + lane], v1 = ucw[r * 64 + lane + 32];
            float m = fmaxf(v0, v1);
#pragma unroll
            for (int o = 16; o; o >>= 1) m = fmaxf(m, __shfl_xor_sync(0xffffffffu, m, o));
            float e0 = __expf(v0 - m), e1 = __expf(v1 - m);
            float s = e0 + e1;
#pragma unroll
            for (int o = 16; o; o >>= 1) s += __shfl_xor_sync(0xffffffffu, s, o);
            g_w[r * 64 + lane] = e0 / s;
            g_w[r * 64 + lane + 32] = e1 / s;
        }
    } else {
        int s = b - 383;
        const float* xr = uem + (size_t)s * 2000;
        const float* mr = msk + (size_t)s * 2000;
        float* Er = g_E + (size_t)s * 2000;
        float m = -3.402823e38f;
        for (int n = u; n < 2000; n += 256)
            if (mr[n] > 0.f) m = fmaxf(m, xr[n]);
        m = bredMax(m);
        float sloc = 0.f;
        for (int n = u; n < 2000; n += 256) {
            float e = (mr[n] > 0.f) ? __expf(xr[n] - m) * mr[n] : 0.f;
            Er[n] = e;
            sloc += e;
        }
        float Z = bredSum(sloc);
        float inv = 1.f / Z;
        for (int n = u; n < 2000; n += 256) Er[n] *= inv;
    }
}

// ================= stage 1: E colmax (8) || pmul dst=1 (32 x 32-row tiles) =================
__global__ __launch_bounds__(256) void k_stage1() {
    const int b = blockIdx.x;
    if (b < 8) {
        int n = b * 256 + threadIdx.x;
        if (n >= 2000) return;
        float m = 0.f;
        for (int s = 0; s < 256; s++) m = fmaxf(m, g_E[(size_t)s * 2000 + n]);
        g_bmaxE[n] = __logf(m);
        float inv = 1.f / m;
        for (int s = 0; s < 256; s++) g_E[(size_t)s * 2000 + n] *= inv;
    } else {
        __shared__ float As[64][68];
        __shared__ float Bs[64][68];
        int rc = b - 8;  // 0..31
        gemm_tile32(g_Ppow, g_Ppow, g_Ppow + 65536, g_Ppt + 65536,
                    (rc >> 2) * 32, (rc & 3) * 64, As, Bs);
    }
}

// ================= stage 2: E transpose (504) || pmul dst=2 count=2 (64 x 32-row) =================
__global__ __launch_bounds__(256) void k_stage2() {
    const int b = blockIdx.x;
    if (b < 504) {
        __shared__ float tile[32][33];
        const int nb = (b % 63) * 32, sb = (b / 63) * 32;
        const int tx = threadIdx.x & 31, tr = threadIdx.x >> 5;
#pragma unroll
        for (int i = tr; i < 32; i += 8) {
            int n = nb + tx;
            tile[i][tx] = (n < 2000) ? g_E[(size_t)(sb + i) * 2000 + n] : 0.f;
        }
        __syncthreads();
#pragma unroll
        for (int i = tr; i < 32; i += 8)
            g_Et[(size_t)(nb + i) * 256 + sb + tx] = tile[tx][i];
    } else {
        __shared__ float As[64][68];
        __shared__ float Bs[64][68];
        int q = b - 504;                 // 0..63
        int z = q >> 5, rc = q & 31;
        gemm_tile32(g_Ppow + (size_t)z * 65536, g_Ppow + 65536,
                    g_Ppow + (size_t)(2 + z) * 65536, g_Ppt + (size_t)(2 + z) * 65536,
                    (rc >> 2) * 32, (rc & 3) * 64, As, Bs);
    }
}

// Batched power (32-row tiles): Ppow[dst+z] = Ppow[z] @ Ppow[dst-1]. grid (4, 8, count)
__global__ __launch_bounds__(256) void k_pmul32(int dst) {
    __shared__ float As[64][68];
    __shared__ float Bs[64][68];
    const int z = blockIdx.z;
    gemm_tile32(g_Ppow + (size_t)z * 65536, g_Ppow + (size_t)(dst - 1) * 65536,
                g_Ppow + (size_t)(dst + z) * 65536, g_Ppt + (size_t)(dst + z) * 65536,
                blockIdx.y * 32, blockIdx.x * 64, As, Bs);
}

// Batched power (64-row tiles). grid (4, 4, count)
__global__ __launch_bounds__(256) void k_pmul(int dst) {
    __shared__ float As[64][68];
    __shared__ float Bs[64][68];
    const int z = blockIdx.z;
    gemm_tile(g_Ppow + (size_t)z * 65536, g_Ppow + (size_t)(dst - 1) * 65536,
              g_Ppow + (size_t)(dst + z) * 65536, g_Ppt + (size_t)(dst + z) * 65536,
              blockIdx.y * 64, blockIdx.x * 64, As, Bs);
}

// ===== Q/backbone chain (all fp32, 32-row tiles) =====
#define QPOW(k) (g_Q + (size_t)(k) * 65536)
#define P64     (g_Ppow + (size_t)63 * 65536)

// qb1: Q2 = P64 @ P64 (32 tiles) || p[64] = p0 @ P64 (8 tiles). grid 40.
__global__ __launch_bounds__(256) void k_qb1() {
    __shared__ float As[64][68];
    __shared__ float Bs[64][68];
    const int b = blockIdx.x;
    if (b < 32)
        gemm_tile32(P64, P64, QPOW(2), nullptr, (b >> 2) * 32, (b & 3) * 64, As, Bs);
    else {
        int q = b - 32;  // 0..7
        gemm_tile32(g_p, P64, g_p + (size_t)64 * 16384, nullptr,
                    (q >> 2) * 32, (q & 3) * 64, As, Bs);
    }
}

// qb2: Q4 = Q2@Q2 (32) || p[128] = p0@Q2 (8) || p[192] = p[64]@Q2 (8). grid 48.
__global__ __launch_bounds__(256) void k_qb2() {
    __shared__ float As[64][68];
    __shared__ float Bs[64][68];
    const int b = blockIdx.x;
    if (b < 32)
        gemm_tile32(QPOW(2), QPOW(2), QPOW(4), nullptr, (b >> 2) * 32, (b & 3) * 64, As, Bs);
    else if (b < 40) {
        int q = b - 32;
        gemm_tile32(g_p, QPOW(2), g_p + (size_t)128 * 16384, nullptr,
                    (q >> 2) * 32, (q & 3) * 64, As, Bs);
    } else {
        int q = b - 40;
        gemm_tile32(g_p + (size_t)64 * 16384, QPOW(2), g_p + (size_t)192 * 16384, nullptr,
                    (q >> 2) * 32, (q & 3) * 64, As, Bs);
    }
}

// qb3: p[256+64j] = p[64j] @ Q4, j=0..3 (32 tiles) || wp[0,:] (1). grid 33.
__global__ __launch_bounds__(256) void k_qb3() {
    const int b = blockIdx.x;
    if (b < 32) {
        __shared__ float As[64][68];
        __shared__ float Bs[64][68];
        int j = b >> 3, q = b & 7;
        gemm_tile32(g_p + (size_t)(64 * j) * 16384, QPOW(4),
                    g_p + (size_t)(256 + 64 * j) * 16384, nullptr,
                    (q >> 2) * 32, (q & 3) * 64, As, Bs);
    } else {
        int s = threadIdx.x;
        float a = 0.f;
#pragma unroll 8
        for (int c = 0; c < 64; c++) a += g_w[c] * g_p[c * 256 + s];
        g_wp[s] = a;
    }
}

// ================= tf32 mma.sync =================
__device__ __forceinline__ void mma_tf32(float* c, const uint32_t* a, const uint32_t* b) {
    asm volatile(
        "mma.sync.aligned.m16n8k8.row.col.f32.tf32.tf32.f32 "
        "{%0,%1,%2,%3}, {%4,%5,%6,%7}, {%8,%9}, {%0,%1,%2,%3};"
        : "+f"(c[0]), "+f"(c[1]), "+f"(c[2]), "+f"(c[3])
        : "r"(a[0]), "r"(a[1]), "r"(a[2]), "r"(a[3]), "r"(b[0]), "r"(b[1]));
}

// Fill via MMA, one CTA per t: p_t[64,256] = p_base[64,256] @ P^i, hid = log(p_t),
// wp[t,:] epilogue in-block. grid: 499, 256 threads = 8 warps (2M x 4N), warp tile 32x64.
__global__ __launch_bounds__(256) void k_fill_mma(float* __restrict__ hid) {
    __shared__ float sA[64][36];
    __shared__ float sB[256][36];
    __shared__ float sw[64];
    const int u = threadIdx.x;
    const int lane = u & 31;
    const int w = u >> 5;
    const int wm = w & 1;     // 2 M-groups of 32 rows
    const int wn = w >> 1;    // 4 N-groups of 64 cols
    const int t = blockIdx.x + 1;
    const int base = ((t - 1) >> 6) << 6;
    const int i = t - base;
    const float* A = g_p + (size_t)base * 16384;
    const float* Bt = g_Ppt + (size_t)(i - 1) * 65536;

    if (u < 64) sw[u] = g_w[t * 64 + u];

    float acc[2][8][4];
#pragma unroll
    for (int mt = 0; mt < 2; mt++)
#pragma unroll
        for (int nt = 0; nt < 8; nt++)
#pragma unroll
            for (int r = 0; r < 4; r++) acc[mt][nt][r] = 0.f;

    const int lr = lane >> 2;
    const int lc = lane & 3;

    for (int ch = 0; ch < 8; ch++) {
        const int k0 = ch * 32;
#pragma unroll
        for (int q = 0; q < 2; q++) {
            int f = q * 256 + u;
            int row = f >> 3, c4 = (f & 7) << 2;
            *(float4*)&sA[row][c4] = *(const float4*)&A[(size_t)row * 256 + k0 + c4];
        }
#pragma unroll
        for (int q = 0; q < 8; q++) {
            int f = q * 256 + u;
            int row = f >> 3, c4 = (f & 7) << 2;
            *(float4*)&sB[row][c4] = *(const float4*)&Bt[(size_t)row * 256 + k0 + c4];
        }
        __syncthreads();
#pragma unroll
        for (int k8 = 0; k8 < 4; k8++) {
            const int kb = k8 * 8;
            uint32_t bfr[8][2];
#pragma unroll
            for (int nt = 0; nt < 8; nt++) {
                const int nrow = wn * 64 + nt * 8 + lr;
                bfr[nt][0] = __float_as_uint(sB[nrow][kb + lc]);
                bfr[nt][1] = __float_as_uint(sB[nrow][kb + lc + 4]);
            }
#pragma unroll
            for (int mt = 0; mt < 2; mt++) {
                const int arow = wm * 32 + mt * 16 + lr;
                uint32_t afr[4];
                afr[0] = __float_as_uint(sA[arow][kb + lc]);
                afr[1] = __float_as_uint(sA[arow + 8][kb + lc]);
                afr[2] = __float_as_uint(sA[arow][kb + lc + 4]);
                afr[3] = __float_as_uint(sA[arow + 8][kb + lc + 4]);
#pragma unroll
                for (int nt = 0; nt < 8; nt++) mma_tf32(acc[mt][nt], afr, bfr[nt]);
            }
        }
        __syncthreads();
    }

    float* pout = g_p + (size_t)t * 16384;
    float* hout = hid + (size_t)t * 16384;
#pragma unroll
    for (int mt = 0; mt < 2; mt++) {
        const int row = wm * 32 + mt * 16 + lr;
#pragma unroll
        for (int nt = 0; nt < 8; nt++) {
            const int col = wn * 64 + nt * 8 + 2 * lc;
            float2 v0 = make_float2(acc[mt][nt][0], acc[mt][nt][1]);
            float2 v1 = make_float2(acc[mt][nt][2], acc[mt][nt][3]);
            *(float2*)&pout[(size_t)row * 256 + col] = v0;
            *(float2*)&pout[(size_t)(row + 8) * 256 + col] = v1;
            *(float2*)&hout[(size_t)row * 256 + col] = make_float2(__logf(v0.x), __logf(v0.y));
            *(float2*)&hout[(size_t)(row + 8) * 256 + col] = make_float2(__logf(v1.x), __logf(v1.y));
        }
    }

    // wp epilogue: wp[t, col] = sum over 64 rows of w[row]*p[row, col]
    float* red = &sB[0][0];  // 16 groups x 256 cols = 4096 floats (fits in sB)
    const int g = wm * 8 + lr;  // rows of group g: wm*32+lr, +8, +16, +24
    float w0 = sw[wm * 32 + lr],      w0b = sw[wm * 32 + lr + 8];
    float w1 = sw[wm * 32 + 16 + lr], w1b = sw[wm * 32 + 16 + lr + 8];
    __syncthreads();   // all reads of sB in MMA loop done before overwrite
#pragma unroll
    for (int nt = 0; nt < 8; nt++) {
        const int col = wn * 64 + nt * 8 + 2 * lc;
#pragma unroll
        for (int d = 0; d < 2; d++) {
            float part = w0 * acc[0][nt][d] + w0b * acc[0][nt][d + 2] +
                         w1 * acc[1][nt][d] + w1b * acc[1][nt][d + 2];
            red[g * 256 + col + d] = part;
        }
    }
    __syncthreads();
#pragma unroll
    for (int h = 8; h > 0; h >>= 1) {
        for (int e = u; e < h * 256; e += 256) red[e] += red[e + h * 256];
        __syncthreads();
    }
    g_wp[(size_t)t * 256 + u] = red[u];
}

// ================= emission GEMM + obs (fused) =================
__global__ __launch_bounds__(256) void k_emis_obs(float* __restrict__ out) {
    __shared__ float pool2[2 * 128 * 36 + 128];
    const int u = threadIdx.x;

    if (blockIdx.y >= 250) {
        float* wsm = pool2;
        const int idx = (blockIdx.y - 250) * 16 + blockIdx.x;
        const int t0 = (idx >> 3) * 16;
        const int n = (idx & 7) * 256 + u;
#pragma unroll
        for (int j = 0; j < 16; j++)
            wsm[j * 256 + u] = (t0 + j < 500) ? g_wp[(size_t)(t0 + j) * 256 + u] : 0.f;
        __syncthreads();
        float acc[16];
#pragma unroll
        for (int j = 0; j < 16; j++) acc[j] = 0.f;
        for (int s = 0; s < 256; s++) {
            float e = (n < 2000) ? g_E[(size_t)s * 2000 + n] : 0.f;
#pragma unroll
            for (int j = 0; j < 16; j++) acc[j] += wsm[j * 256 + s] * e;
        }
        if (n < 2000) {
            float bm = g_bmaxE[n];
#pragma unroll
            for (int j = 0; j < 16; j++)
                if (t0 + j < 500) out[(size_t)(t0 + j) * 2000 + n] = __logf(acc[j]) + bm;
        }
        return;
    }

    float (*sA)[36] = (float(*)[36])pool2;
    float (*sB)[36] = (float(*)[36])(pool2 + 128 * 36);
    float* sBM = pool2 + 2 * 128 * 36;

    const int lane = u & 31;
    const int w = u >> 5;
    const int wm = w & 3;
    const int wn = w >> 2;
    const int n0 = blockIdx.x * 128;
    const int r0 = blockIdx.y * 128;

    if (u < 128) sBM[u] = g_bmaxE[n0 + u];

    float acc[2][8][4];
#pragma unroll
    for (int mt = 0; mt < 2; mt++)
#pragma unroll
        for (int nt = 0; nt < 8; nt++)
#pragma unroll
            for (int r = 0; r < 4; r++) acc[mt][nt][r] = 0.f;

    const int lr = lane >> 2;
    const int lc = lane & 3;

    for (int ch = 0; ch < 8; ch++) {
        const int k0 = ch * 32;
#pragma unroll
        for (int q = 0; q < 4; q++) {
            int f = q * 256 + u;
            int row = f >> 3, c4 = (f & 7) << 2;
            *(float4*)&sA[row][c4] = *(const float4*)&g_p[(size_t)(r0 + row) * 256 + k0 + c4];
            *(float4*)&sB[row][c4] = *(const float4*)&g_Et[(size_t)(n0 + row) * 256 + k0 + c4];
        }
        __syncthreads();
#pragma unroll
        for (int k8 = 0; k8 < 4; k8++) {
            const int kb = k8 * 8;
            uint32_t bfr[8][2];
#pragma unroll
            for (int nt = 0; nt < 8; nt++) {
                const int nrow = wn * 64 + nt * 8 + lr;
                bfr[nt][0] = __float_as_uint(sB[nrow][kb + lc]);
                bfr[nt][1] = __float_as_uint(sB[nrow][kb + lc + 4]);
            }
#pragma unroll
            for (int mt = 0; mt < 2; mt++) {
                const int arow = wm * 32 + mt * 16 + lr;
                uint32_t afr[4];
                afr[0] = __float_as_uint(sA[arow][kb + lc]);
                afr[1] = __float_as_uint(sA[arow + 8][kb + lc]);
                afr[2] = __float_as_uint(sA[arow][kb + lc + 4]);
                afr[3] = __float_as_uint(sA[arow + 8][kb + lc + 4]);
#pragma unroll
                for (int nt = 0; nt < 8; nt++) mma_tf32(acc[mt][nt], afr, bfr[nt]);
            }
        }
        __syncthreads();
    }

    float* obsp = out + 1000000u;
#pragma unroll
    for (int mt = 0; mt < 2; mt++) {
        const int row = r0 + wm * 32 + mt * 16 + lr;
#pragma unroll
        for (int nt = 0; nt < 8; nt++) {
            const int col = wn * 64 + nt * 8 + 2 * lc;
            const int n = n0 + col;
            if (n < 2000) {
                float2 v0, v1;
                v0.x = __logf(acc[mt][nt][0]) + sBM[col];
                v0.y = __logf(acc[mt][nt][1]) + sBM[col + 1];
                v1.x = __logf(acc[mt][nt][2]) + sBM[col];
                v1.y = __logf(acc[mt][nt][3]) + sBM[col + 1];
                *(float2*)&obsp[(size_t)row * 2000 + n] = v0;
                *(float2*)&obsp[(size_t)(row + 8) * 2000 + n] = v1;
            }
        }
    }
}

// ================= launch =================
extern "C" void kernel_launch(void* const* d_in, const int* in_sizes, int n_in,
                              void* d_out, int out_size) {
    const float* usi = (const float*)d_in[0];  // [64,256]
    const float* ucw = (const float*)d_in[1];  // [500,64]
    const float* uem = (const float*)d_in[2];  // [256,2000]
    const float* utm = (const float*)d_in[3];  // [256,256]
    const float* msk = (const float*)d_in[4];  // [256,2000]
    float* out = (float*)d_out;
    float* hid = out + 65000000u;

    k_stage0<<<639, 256>>>(usi, ucw, utm, uem, msk, hid);
    k_stage1<<<40, 256>>>();
    k_stage2<<<568, 256>>>();

    k_pmul32<<<dim3(4, 8, 4), 256>>>(4);    // P^5..8
    k_pmul32<<<dim3(4, 8, 8), 256>>>(8);    // P^9..16
    k_pmul<<<dim3(4, 4, 16), 256>>>(16);    // P^17..32
    k_pmul<<<dim3(4, 4, 32), 256>>>(32);    // P^33..64

    k_qb1<<<40, 256>>>();
    k_qb2<<<48, 256>>>();
    k_qb3<<<33, 256>>>();

    k_fill_mma<<<499, 256>>>(hid);
    k_emis_obs<<<dim3(16, 266), 256>>>(out);
}